// round 2
// baseline (speedup 1.0000x reference)
#include <cuda_runtime.h>

#define NPTS   100000
#define CC     64
#define MPAD   60000
#define NOFF   26
#define CENTER_K 13

// ---------------------------------------------------------------------------
// Kernel A: dense center GEMM  out = feats @ W[13]   (also initializes out)
// Block = 256 threads = 8 warps; each warp computes 4 consecutive rows.
// Thread layout inside a warp: h = lane/16 selects row pair {2h, 2h+1},
// lane16 = lane%16 selects 4 contiguous output columns.
// ---------------------------------------------------------------------------
__global__ __launch_bounds__(256)
void center_gemm_kernel(const float* __restrict__ feats,
                        const float* __restrict__ weight,
                        float* __restrict__ out) {
    __shared__ float4 sw4[1024];          // W[13] : 64x64 f32 = 16 KB
    __shared__ float  sf[8][4][72];       // per-warp 4 input rows (pad 72 vs bank conflicts)

    const float4* wk = (const float4*)(weight + (size_t)CENTER_K * CC * CC);
    for (int i = threadIdx.x; i < 1024; i += 256) sw4[i] = wk[i];
    __syncthreads();

    const int warp   = threadIdx.x >> 5;
    const int lane   = threadIdx.x & 31;
    const int lane16 = lane & 15;
    const int h      = lane >> 4;

    const int row0 = (blockIdx.x * 8 + warp) * 4;
    if (row0 >= NPTS) return;

    // cooperative load of 4 feature rows into shared (rows h, h+2 per lane half)
#pragma unroll
    for (int i = 0; i < 2; i++) {
        const int r = h + 2 * i;
        float4 v = *(const float4*)(feats + (size_t)(row0 + r) * CC + lane16 * 4);
        *(float4*)&sf[warp][r][lane16 * 4] = v;
    }
    __syncwarp();

    float acc[2][4] = {{0.f,0.f,0.f,0.f},{0.f,0.f,0.f,0.f}};
#pragma unroll 8
    for (int c = 0; c < CC; c++) {
        const float  f0 = sf[warp][2*h    ][c];
        const float  f1 = sf[warp][2*h + 1][c];
        const float4 w4 = sw4[c * 16 + lane16];
        acc[0][0] += f0 * w4.x; acc[0][1] += f0 * w4.y;
        acc[0][2] += f0 * w4.z; acc[0][3] += f0 * w4.w;
        acc[1][0] += f1 * w4.x; acc[1][1] += f1 * w4.y;
        acc[1][2] += f1 * w4.z; acc[1][3] += f1 * w4.w;
    }

    *(float4*)(out + (size_t)(row0 + 2*h    ) * CC + lane16 * 4) =
        make_float4(acc[0][0], acc[0][1], acc[0][2], acc[0][3]);
    *(float4*)(out + (size_t)(row0 + 2*h + 1) * CC + lane16 * 4) =
        make_float4(acc[1][0], acc[1][1], acc[1][2], acc[1][3]);
}

// ---------------------------------------------------------------------------
// Kernel B: per-offset gather -> 4-row GEMM -> red.global.add.v4 scatter.
// grid = (CHUNKS, 26). Each block owns one offset k, stages W_k in SMEM once,
// then grid-strides over the 60000 map slots in 4-row warp groups.
// Valid entries form a contiguous prefix per offset row, so src0<0 => skip.
// ---------------------------------------------------------------------------
__global__ __launch_bounds__(256)
void scatter_conv_kernel(const float* __restrict__ feats,
                         const float* __restrict__ weight,
                         const int*   __restrict__ imap,
                         const int*   __restrict__ omap,
                         float* __restrict__ out) {
    __shared__ float4 sw4[1024];
    __shared__ float  sf[8][4][72];

    const int k = blockIdx.y;
    const int w = (k < CENTER_K) ? k : k + 1;   // skip center tap in weight tensor
    const float4* wk = (const float4*)(weight + (size_t)w * CC * CC);
    for (int i = threadIdx.x; i < 1024; i += 256) sw4[i] = wk[i];
    __syncthreads();

    const int* __restrict__ im = imap + (size_t)k * MPAD;
    const int* __restrict__ om = omap + (size_t)k * MPAD;

    const int warp   = threadIdx.x >> 5;
    const int lane   = threadIdx.x & 31;
    const int lane16 = lane & 15;
    const int h      = lane >> 4;

    const int stride = gridDim.x * 8 * 4;

    for (int m = (blockIdx.x * 8 + warp) * 4; m < MPAD; m += stride) {
        // lanes 0-3 fetch imap, lanes 4-7 fetch omap for the 4 rows
        int v = -1;
        if (lane < 4)      v = im[m + lane];
        else if (lane < 8) v = om[m + lane - 4];

        const int src0 = __shfl_sync(0xffffffffu, v, 0);
        if (src0 < 0) continue;               // validity is a prefix: whole group empty

        // gather 4 source rows into shared (zero-fill invalid tail rows)
        __syncwarp();
#pragma unroll
        for (int i = 0; i < 2; i++) {
            const int r = h + 2 * i;
            const int s = __shfl_sync(0xffffffffu, v, r);
            float4 val = make_float4(0.f, 0.f, 0.f, 0.f);
            if (s >= 0)
                val = *(const float4*)(feats + (size_t)s * CC + lane16 * 4);
            *(float4*)&sf[warp][r][lane16 * 4] = val;
        }
        __syncwarp();

        float acc[2][4] = {{0.f,0.f,0.f,0.f},{0.f,0.f,0.f,0.f}};
#pragma unroll 8
        for (int c = 0; c < CC; c++) {
            const float  f0 = sf[warp][2*h    ][c];
            const float  f1 = sf[warp][2*h + 1][c];
            const float4 w4 = sw4[c * 16 + lane16];
            acc[0][0] += f0 * w4.x; acc[0][1] += f0 * w4.y;
            acc[0][2] += f0 * w4.z; acc[0][3] += f0 * w4.w;
            acc[1][0] += f1 * w4.x; acc[1][1] += f1 * w4.y;
            acc[1][2] += f1 * w4.z; acc[1][3] += f1 * w4.w;
        }

        // coalesced 256B vectored reduction per valid row
#pragma unroll
        for (int r2 = 0; r2 < 2; r2++) {
            const int d = __shfl_sync(0xffffffffu, v, 4 + 2*h + r2);
            if (d >= 0) {
                float* p = out + (size_t)d * CC + lane16 * 4;
                asm volatile("red.global.add.v4.f32 [%0], {%1, %2, %3, %4};"
                             :: "l"(p),
                                "f"(acc[r2][0]), "f"(acc[r2][1]),
                                "f"(acc[r2][2]), "f"(acc[r2][3])
                             : "memory");
            }
        }
    }
}

// ---------------------------------------------------------------------------
// kernel_launch: center GEMM (writes/initializes out), then scatter adds.
// Same stream -> ordered; graph-capturable (launches only, no allocs/syncs).
// ---------------------------------------------------------------------------
extern "C" void kernel_launch(void* const* d_in, const int* in_sizes, int n_in,
                              void* d_out, int out_size) {
    const float* feats  = (const float*)d_in[0];
    const float* weight = (const float*)d_in[1];
    const int*   imap   = (const int*)d_in[2];
    const int*   omap   = (const int*)d_in[3];
    float*       out    = (float*)d_out;

    center_gemm_kernel<<<(NPTS + 31) / 32, 256>>>(feats, weight, out);

    dim3 grid(48, NOFF);
    scatter_conv_kernel<<<grid, 256>>>(feats, weight, imap, omap, out);
}

// round 3
// speedup vs baseline: 1.7688x; 1.7688x over previous
#include <cuda_runtime.h>

#define NPTS   100000
#define CC     64
#define MPAD   60000
#define NOFF   26
#define CENTER_K 13
#define WARPS  8

__device__ __forceinline__ void fma4(float4& a, float s, const float4& w) {
    a.x += s * w.x; a.y += s * w.y; a.z += s * w.z; a.w += s * w.w;
}

// ---------------------------------------------------------------------------
// Kernel A: dense center GEMM  out = feats @ W[13]   (also initializes out).
// 8 rows per warp, float4 register blocking: per 4 c-steps each thread does
// 8 LDS.128 (4 w + 4 f) for 64 FFMAs.
// ---------------------------------------------------------------------------
__global__ __launch_bounds__(256)
void center_gemm_kernel(const float* __restrict__ feats,
                        const float* __restrict__ weight,
                        float* __restrict__ out) {
    __shared__ float4 sw4[CC * 16];        // W[13]: 64x64 f32 = 16 KB
    __shared__ float  sf[WARPS][8][68];    // 8 rows per warp, padded

    const float4* wk = (const float4*)(weight + (size_t)CENTER_K * CC * CC);
    for (int i = threadIdx.x; i < CC * 16; i += 256) sw4[i] = wk[i];
    __syncthreads();

    const int warp   = threadIdx.x >> 5;
    const int lane   = threadIdx.x & 31;
    const int lane16 = lane & 15;
    const int h      = lane >> 4;
    const int rb     = 4 * h;              // this half's 4 rows within the 8

    const int row0 = (blockIdx.x * WARPS + warp) * 8;
    if (row0 >= NPTS) return;

    // each half loads its own 4 rows into shared
#pragma unroll
    for (int i = 0; i < 4; i++) {
        const int r = rb + i;
        float4 v = make_float4(0.f, 0.f, 0.f, 0.f);
        if (row0 + r < NPTS)
            v = *(const float4*)(feats + (size_t)(row0 + r) * CC + lane16 * 4);
        *(float4*)&sf[warp][r][lane16 * 4] = v;
    }
    __syncwarp();

    float4 acc[4];
#pragma unroll
    for (int r = 0; r < 4; r++) acc[r] = make_float4(0.f, 0.f, 0.f, 0.f);

#pragma unroll 4
    for (int c4 = 0; c4 < 16; c4++) {
        const float4 w0 = sw4[(c4 * 4 + 0) * 16 + lane16];
        const float4 w1 = sw4[(c4 * 4 + 1) * 16 + lane16];
        const float4 w2 = sw4[(c4 * 4 + 2) * 16 + lane16];
        const float4 w3 = sw4[(c4 * 4 + 3) * 16 + lane16];
#pragma unroll
        for (int r = 0; r < 4; r++) {
            const float4 f = *(const float4*)&sf[warp][rb + r][c4 * 4];
            fma4(acc[r], f.x, w0); fma4(acc[r], f.y, w1);
            fma4(acc[r], f.z, w2); fma4(acc[r], f.w, w3);
        }
    }

#pragma unroll
    for (int r = 0; r < 4; r++) {
        if (row0 + rb + r < NPTS)
            *(float4*)(out + (size_t)(row0 + rb + r) * CC + lane16 * 4) = acc[r];
    }
}

// ---------------------------------------------------------------------------
// Kernel B: per-offset gather -> 8-row warp GEMM -> red.global.add.v4 scatter.
// grid = (CHUNKS, 26). Valid entries are a contiguous prefix per offset row,
// so slot0 < 0 => whole 8-row group empty.
// ---------------------------------------------------------------------------
__global__ __launch_bounds__(256)
void scatter_conv_kernel(const float* __restrict__ feats,
                         const float* __restrict__ weight,
                         const int*   __restrict__ imap,
                         const int*   __restrict__ omap,
                         float* __restrict__ out) {
    __shared__ float4 sw4[CC * 16];
    __shared__ float  sf[WARPS][8][68];

    const int k = blockIdx.y;
    const int w = (k < CENTER_K) ? k : k + 1;    // skip center tap
    const float4* wk = (const float4*)(weight + (size_t)w * CC * CC);
    for (int i = threadIdx.x; i < CC * 16; i += 256) sw4[i] = wk[i];
    __syncthreads();

    const int* __restrict__ im = imap + (size_t)k * MPAD;
    const int* __restrict__ om = omap + (size_t)k * MPAD;

    const int warp   = threadIdx.x >> 5;
    const int lane   = threadIdx.x & 31;
    const int lane16 = lane & 15;
    const int h      = lane >> 4;
    const int rb     = 4 * h;

    const int stride = gridDim.x * WARPS * 8;

    for (int m = (blockIdx.x * WARPS + warp) * 8; m < MPAD; m += stride) {
        // lanes 0-7: imap for the 8 rows; lanes 8-15: omap
        int v = -1;
        if (lane < 8)       v = im[m + lane];
        else if (lane < 16) v = om[m + lane - 8];

        if (__shfl_sync(0xffffffffu, v, 0) < 0) continue;  // prefix validity

        // gather: half h loads its own rows rb..rb+3 (zero-fill invalid)
#pragma unroll
        for (int i = 0; i < 4; i++) {
            const int r = rb + i;
            const int s = __shfl_sync(0xffffffffu, v, r);
            float4 val = make_float4(0.f, 0.f, 0.f, 0.f);
            if (s >= 0)
                val = *(const float4*)(feats + (size_t)s * CC + lane16 * 4);
            *(float4*)&sf[warp][r][lane16 * 4] = val;
        }
        __syncwarp();

        float4 acc[4];
#pragma unroll
        for (int r = 0; r < 4; r++) acc[r] = make_float4(0.f, 0.f, 0.f, 0.f);

#pragma unroll 4
        for (int c4 = 0; c4 < 16; c4++) {
            const float4 w0 = sw4[(c4 * 4 + 0) * 16 + lane16];
            const float4 w1 = sw4[(c4 * 4 + 1) * 16 + lane16];
            const float4 w2 = sw4[(c4 * 4 + 2) * 16 + lane16];
            const float4 w3 = sw4[(c4 * 4 + 3) * 16 + lane16];
#pragma unroll
            for (int r = 0; r < 4; r++) {
                const float4 f = *(const float4*)&sf[warp][rb + r][c4 * 4];
                fma4(acc[r], f.x, w0); fma4(acc[r], f.y, w1);
                fma4(acc[r], f.z, w2); fma4(acc[r], f.w, w3);
            }
        }

        // coalesced 256B vectored reduction per valid row
#pragma unroll
        for (int r = 0; r < 4; r++) {
            const int d = __shfl_sync(0xffffffffu, v, 8 + rb + r);
            if (d >= 0) {
                float* p = out + (size_t)d * CC + lane16 * 4;
                asm volatile("red.global.add.v4.f32 [%0], {%1, %2, %3, %4};"
                             :: "l"(p),
                                "f"(acc[r].x), "f"(acc[r].y),
                                "f"(acc[r].z), "f"(acc[r].w)
                             : "memory");
            }
        }
        __syncwarp();   // sf reuse guard before next gather
    }
}

// ---------------------------------------------------------------------------
// kernel_launch: center GEMM (initializes out), then scatter adds. Same
// stream -> ordered; graph-capturable (launches only).
// ---------------------------------------------------------------------------
extern "C" void kernel_launch(void* const* d_in, const int* in_sizes, int n_in,
                              void* d_out, int out_size) {
    const float* feats  = (const float*)d_in[0];
    const float* weight = (const float*)d_in[1];
    const int*   imap   = (const int*)d_in[2];
    const int*   omap   = (const int*)d_in[3];
    float*       out    = (float*)d_out;

    center_gemm_kernel<<<(NPTS + 63) / 64, 256>>>(feats, weight, out);

    dim3 grid(48, NOFF);
    scatter_conv_kernel<<<grid, 256>>>(feats, weight, imap, omap, out);
}

// round 4
// speedup vs baseline: 1.7725x; 1.0021x over previous
#include <cuda_runtime.h>

#define NPTS   100000
#define CC     64
#define MPAD   60000
#define NOFF   26
#define CENTER_K 13
#define WARPS  8

__device__ __forceinline__ void fma4(float4& a, float s, const float4& w) {
    a.x += s * w.x; a.y += s * w.y; a.z += s * w.z; a.w += s * w.w;
}

// ---------------------------------------------------------------------------
// Kernel A: dense center GEMM  out = feats @ W[13]   (also initializes out).
// 8 rows per warp, float4 register blocking: per 4 c-steps each thread does
// 8 LDS.128 (4 w + 4 f) for 64 FFMAs.
// ---------------------------------------------------------------------------
__global__ __launch_bounds__(256)
void center_gemm_kernel(const float* __restrict__ feats,
                        const float* __restrict__ weight,
                        float* __restrict__ out) {
    __shared__ float4 sw4[CC * 16];        // W[13]: 64x64 f32 = 16 KB
    __shared__ float  sf[WARPS][8][68];    // 8 rows per warp, padded

    const float4* wk = (const float4*)(weight + (size_t)CENTER_K * CC * CC);
    for (int i = threadIdx.x; i < CC * 16; i += 256) sw4[i] = wk[i];
    __syncthreads();

    const int warp   = threadIdx.x >> 5;
    const int lane   = threadIdx.x & 31;
    const int lane16 = lane & 15;
    const int h      = lane >> 4;
    const int rb     = 4 * h;              // this half's 4 rows within the 8

    const int row0 = (blockIdx.x * WARPS + warp) * 8;
    if (row0 >= NPTS) return;

    // each half loads its own 4 rows into shared
#pragma unroll
    for (int i = 0; i < 4; i++) {
        const int r = rb + i;
        float4 v = make_float4(0.f, 0.f, 0.f, 0.f);
        if (row0 + r < NPTS)
            v = *(const float4*)(feats + (size_t)(row0 + r) * CC + lane16 * 4);
        *(float4*)&sf[warp][r][lane16 * 4] = v;
    }
    __syncwarp();

    float4 acc[4];
#pragma unroll
    for (int r = 0; r < 4; r++) acc[r] = make_float4(0.f, 0.f, 0.f, 0.f);

#pragma unroll 4
    for (int c4 = 0; c4 < 16; c4++) {
        const float4 w0 = sw4[(c4 * 4 + 0) * 16 + lane16];
        const float4 w1 = sw4[(c4 * 4 + 1) * 16 + lane16];
        const float4 w2 = sw4[(c4 * 4 + 2) * 16 + lane16];
        const float4 w3 = sw4[(c4 * 4 + 3) * 16 + lane16];
#pragma unroll
        for (int r = 0; r < 4; r++) {
            const float4 f = *(const float4*)&sf[warp][rb + r][c4 * 4];
            fma4(acc[r], f.x, w0); fma4(acc[r], f.y, w1);
            fma4(acc[r], f.z, w2); fma4(acc[r], f.w, w3);
        }
    }

#pragma unroll
    for (int r = 0; r < 4; r++) {
        if (row0 + rb + r < NPTS)
            *(float4*)(out + (size_t)(row0 + rb + r) * CC + lane16 * 4) = acc[r];
    }
}

// ---------------------------------------------------------------------------
// Kernel B: per-offset gather -> 8-row warp GEMM -> red.global.add.v4 scatter.
// grid = (CHUNKS, 26). Valid entries are a contiguous prefix per offset row,
// so slot0 < 0 => whole 8-row group empty.
// ---------------------------------------------------------------------------
__global__ __launch_bounds__(256)
void scatter_conv_kernel(const float* __restrict__ feats,
                         const float* __restrict__ weight,
                         const int*   __restrict__ imap,
                         const int*   __restrict__ omap,
                         float* __restrict__ out) {
    __shared__ float4 sw4[CC * 16];
    __shared__ float  sf[WARPS][8][68];

    const int k = blockIdx.y;
    const int w = (k < CENTER_K) ? k : k + 1;    // skip center tap
    const float4* wk = (const float4*)(weight + (size_t)w * CC * CC);
    for (int i = threadIdx.x; i < CC * 16; i += 256) sw4[i] = wk[i];
    __syncthreads();

    const int* __restrict__ im = imap + (size_t)k * MPAD;
    const int* __restrict__ om = omap + (size_t)k * MPAD;

    const int warp   = threadIdx.x >> 5;
    const int lane   = threadIdx.x & 31;
    const int lane16 = lane & 15;
    const int h      = lane >> 4;
    const int rb     = 4 * h;

    const int stride = gridDim.x * WARPS * 8;

    for (int m = (blockIdx.x * WARPS + warp) * 8; m < MPAD; m += stride) {
        // lanes 0-7: imap for the 8 rows; lanes 8-15: omap
        int v = -1;
        if (lane < 8)       v = im[m + lane];
        else if (lane < 16) v = om[m + lane - 8];

        if (__shfl_sync(0xffffffffu, v, 0) < 0) continue;  // prefix validity

        // gather: half h loads its own rows rb..rb+3 (zero-fill invalid)
#pragma unroll
        for (int i = 0; i < 4; i++) {
            const int r = rb + i;
            const int s = __shfl_sync(0xffffffffu, v, r);
            float4 val = make_float4(0.f, 0.f, 0.f, 0.f);
            if (s >= 0)
                val = *(const float4*)(feats + (size_t)s * CC + lane16 * 4);
            *(float4*)&sf[warp][r][lane16 * 4] = val;
        }
        __syncwarp();

        float4 acc[4];
#pragma unroll
        for (int r = 0; r < 4; r++) acc[r] = make_float4(0.f, 0.f, 0.f, 0.f);

#pragma unroll 4
        for (int c4 = 0; c4 < 16; c4++) {
            const float4 w0 = sw4[(c4 * 4 + 0) * 16 + lane16];
            const float4 w1 = sw4[(c4 * 4 + 1) * 16 + lane16];
            const float4 w2 = sw4[(c4 * 4 + 2) * 16 + lane16];
            const float4 w3 = sw4[(c4 * 4 + 3) * 16 + lane16];
#pragma unroll
            for (int r = 0; r < 4; r++) {
                const float4 f = *(const float4*)&sf[warp][rb + r][c4 * 4];
                fma4(acc[r], f.x, w0); fma4(acc[r], f.y, w1);
                fma4(acc[r], f.z, w2); fma4(acc[r], f.w, w3);
            }
        }

        // coalesced 256B vectored reduction per valid row
#pragma unroll
        for (int r = 0; r < 4; r++) {
            const int d = __shfl_sync(0xffffffffu, v, 8 + rb + r);
            if (d >= 0) {
                float* p = out + (size_t)d * CC + lane16 * 4;
                asm volatile("red.global.add.v4.f32 [%0], {%1, %2, %3, %4};"
                             :: "l"(p),
                                "f"(acc[r].x), "f"(acc[r].y),
                                "f"(acc[r].z), "f"(acc[r].w)
                             : "memory");
            }
        }
        __syncwarp();   // sf reuse guard before next gather
    }
}

// ---------------------------------------------------------------------------
// kernel_launch: center GEMM (initializes out), then scatter adds. Same
// stream -> ordered; graph-capturable (launches only).
// ---------------------------------------------------------------------------
extern "C" void kernel_launch(void* const* d_in, const int* in_sizes, int n_in,
                              void* d_out, int out_size) {
    const float* feats  = (const float*)d_in[0];
    const float* weight = (const float*)d_in[1];
    const int*   imap   = (const int*)d_in[2];
    const int*   omap   = (const int*)d_in[3];
    float*       out    = (float*)d_out;

    center_gemm_kernel<<<(NPTS + 63) / 64, 256>>>(feats, weight, out);

    dim3 grid(48, NOFF);
    scatter_conv_kernel<<<grid, 256>>>(feats, weight, imap, omap, out);
}